// round 14
// baseline (speedup 1.0000x reference)
#include <cuda_runtime.h>
#include <cuda_fp16.h>
#include <cstdint>

// Problem constants
#define B_  128
#define T_  100
#define E_  128
#define F_  700
#define S_  400
#define V_  10000

#define FH_LDA 720
#define SH_LDA 424
#define HI_LDA 704

#define KS_CELL 3
#define KS_SLOW 5
#define GRID_P  132          // persistent grid (44*3)

typedef __half fp16;

// ---------------------------------------------------------------------------
// Static device scratch
// ---------------------------------------------------------------------------
__device__ float g_fh[B_ * F_];
__device__ float g_fc[B_ * F_];
__device__ float g_sh[B_ * S_];
__device__ float g_sc[B_ * S_];
__device__ float g_z [KS_CELL * B_ * 4 * F_];
__device__ float g_zS[KS_SLOW * B_ * 4 * S_];

__device__ fp16 g_xh[B_ * T_ * E_], g_xm[B_ * T_ * E_];
__device__ fp16 g_fhh[B_ * FH_LDA], g_fhm[B_ * FH_LDA];
__device__ fp16 g_shh[B_ * SH_LDA], g_shm[B_ * SH_LDA];
__device__ fp16 g_hih[(size_t)B_ * T_ * HI_LDA];          // hist high split only

__device__ fp16 g_W0h[(size_t)4 * F_ * 832],  g_W0m[(size_t)4 * F_ * 832];
__device__ fp16 g_WSh[(size_t)4 * S_ * 1120], g_WSm[(size_t)4 * S_ * 1120];
__device__ fp16 g_W1h[(size_t)4 * F_ * 1120], g_W1m[(size_t)4 * F_ * 1120];
__device__ fp16 g_Woh[(size_t)V_ * 704];

// Grid barrier state: per-CTA arrival flags (32B stride) + release word
__device__ unsigned g_flags[GRID_P * 8];
__device__ unsigned g_bargen;

// ---------------------------------------------------------------------------
// Helpers
// ---------------------------------------------------------------------------
__device__ __forceinline__ uint32_t smem_u32(const void* p) {
    uint32_t a;
    asm("{ .reg .u64 t; cvta.to.shared.u64 t, %1; cvt.u32.u64 %0, t; }" : "=r"(a) : "l"(p));
    return a;
}
__device__ __forceinline__ void split2(float x, fp16& h, fp16& m) {
    h = __float2half_rn(x);
    m = __float2half_rn(x - __half2float(h));
}
__device__ __forceinline__ void mma_fp16(float c[4], const uint32_t a[4], const uint32_t b[2]) {
    asm volatile("mma.sync.aligned.m16n8k16.row.col.f32.f16.f16.f32 "
                 "{%0,%1,%2,%3}, {%4,%5,%6,%7}, {%8,%9}, {%0,%1,%2,%3};"
                 : "+f"(c[0]), "+f"(c[1]), "+f"(c[2]), "+f"(c[3])
                 : "r"(a[0]), "r"(a[1]), "r"(a[2]), "r"(a[3]), "r"(b[0]), "r"(b[1]));
}
#define CP16(dst, src, sz) \
    asm volatile("cp.async.cg.shared.global [%0], [%1], 16, %2;" \
                 :: "r"(dst), "l"(src), "r"(sz))
#define CP_COMMIT() asm volatile("cp.async.commit_group;" ::: "memory")
#define CP_WAIT1()  asm volatile("cp.async.wait_group 1;" ::: "memory")
#define CP_WAIT0()  asm volatile("cp.async.wait_group 0;" ::: "memory")

#define ARP    80
#define ASZ    (128 * ARP)           // 10240 bytes per A split-buffer
#define BSZ64  (64 * ARP)            // 5120  bytes per B split-buffer (BN=64)
#define GBBASE (4 * ASZ)             // 40960: B region base in recurrence GEMM
#define PWOFF  (4 * ASZ + 4 * BSZ64) // 61440: pw region base
#define SMP    (PWOFF + 4 * F_ * 4 + 320)  // 72960

// ---------------------------------------------------------------------------
// Fast grid barrier: parallel flag stores + CTA0 gather + single release word.
// ---------------------------------------------------------------------------
__device__ __forceinline__ void gbar(unsigned& mygen) {
    mygen++;
    __syncthreads();
    __threadfence();
    if (threadIdx.x == 0)
        *((volatile unsigned*)&g_flags[blockIdx.x * 8]) = mygen;
    if (blockIdx.x == 0) {
        if (threadIdx.x < GRID_P) {
            volatile unsigned* f = &g_flags[threadIdx.x * 8];
            while (*f < mygen) {}
        }
        __syncthreads();
        if (threadIdx.x == 0) {
            __threadfence();
            *((volatile unsigned*)&g_bargen) = mygen;
        }
    } else {
        if (threadIdx.x == 0) {
            volatile unsigned* g = &g_bargen;
            while (*g < mygen) {}
        }
    }
    __syncthreads();
    __threadfence();
}

// ---------------------------------------------------------------------------
// Prefetch first-chunk tiles of the NEXT gemm phase (B always; A iff kz==kzA,
// whose first chunk touches only state that is already final).
// Issued before the phase barrier; flights overlap barrier + pw.
// ---------------------------------------------------------------------------
__device__ void prefetch_gemm(char* sm,
    const fp16* __restrict__ A1h, const fp16* __restrict__ A1m, int lda1, int K1p,
    const fp16* __restrict__ A2h, const fp16* __restrict__ A2m, int lda2,
    const fp16* __restrict__ Wh, const fp16* __restrict__ Wm, int ldw,
    int Kpad, int N, int tnc, int KS, int kzA)
{
    const uint32_t sbase = smem_u32(sm);
    const int tid = threadIdx.x;
    const int cta = blockIdx.x;
    if (cta < tnc * KS) {
        const int n0  = (cta % tnc) * 64;
        const int kz  = cta / tnc;
        const int nk  = Kpad >> 5;
        const int nkq = (nk + KS - 1) / KS;
        const int i0  = kz * nkq;
        if (i0 < nk) {
            const int k0  = i0 << 5;
            const int buf = i0 & 1;
            #pragma unroll
            for (int it = 0; it < 2; it++) {
                const int r  = tid >> 2;
                const int c4 = tid & 3;
                const int n  = n0 + r;
                const int nc = (n < N) ? n : (N - 1);
                const fp16* src = ((it == 0) ? Wh : Wm) + (long)nc * ldw + k0 + (c4 << 3);
                CP16(sbase + GBBASE + it * (2 * BSZ64) + buf * BSZ64 + r * ARP + c4 * 16,
                     src, (n < N) ? 16 : 0);
            }
            if (kz == kzA) {
                #pragma unroll
                for (int it = 0; it < 4; it++) {
                    const int sp  = it >> 1;
                    const int idx = ((it & 1) << 8) + tid;
                    const int r   = idx >> 2;
                    const int c4  = idx & 3;
                    const int gk  = k0 + (c4 << 3);
                    const fp16* src = (gk < K1p)
                        ? ((sp == 0) ? A1h : A1m) + r * lda1 + gk
                        : ((sp == 0) ? A2h : A2m) + r * lda2 + (gk - K1p);
                    CP16(sbase + sp * (2 * ASZ) + buf * ASZ + r * ARP + c4 * 16, src, 16);
                }
            }
        }
    }
    CP_COMMIT();
}

// ---------------------------------------------------------------------------
// GEMM phase (device fn), BN=64, fp16 2-way split, 3 products:
//   HM + MH chained in-MMA (~2^-11), H*H via zero-C MMA + IEEE FADD.
// pre=1: first chunk's B (and A iff kz==kzA) was prefetched.
// ---------------------------------------------------------------------------
__device__ void gemm_phase(char* sm,
    const fp16* __restrict__ A1h, const fp16* __restrict__ A1m,
    int lda1, int K1p,
    const fp16* __restrict__ A2h, const fp16* __restrict__ A2m,
    int lda2,
    const fp16* __restrict__ Wh, const fp16* __restrict__ Wm,
    int ldw,
    float* __restrict__ C, int ldc, int pstride,
    int Kpad, int N, int tnc, int KS, int pre, int kzA)
{
    constexpr int NT = 4;

    const int cta = blockIdx.x;
    if (cta >= tnc * KS) return;

    const uint32_t sbase = smem_u32(sm);
    const int tid  = threadIdx.x;
    const int wid  = tid >> 5;
    const int lane = tid & 31;
    const int wm   = wid & 3;
    const int wn   = wid >> 2;
    const int n0   = (cta % tnc) * 64;
    const int kz   = cta / tnc;
    const int nk   = Kpad >> 5;
    const int nkq  = (nk + KS - 1) / KS;
    const int i0   = kz * nkq;
    const int i1   = (i0 + nkq < nk) ? (i0 + nkq) : nk;

    const fp16* A1s[2] = {A1h, A1m};
    const fp16* A2s[2] = {A2h, A2m};
    const fp16* Ws [2] = {Wh,  Wm};
    const int skipA0 = pre && (kz == kzA);

    float acc[2][NT][4], accs[2][NT][4];
    #pragma unroll
    for (int mt = 0; mt < 2; mt++)
        #pragma unroll
        for (int nt = 0; nt < NT; nt++)
            #pragma unroll
            for (int r = 0; r < 4; r++) { acc[mt][nt][r] = 0.0f; accs[mt][nt][r] = 0.0f; }

    auto load_chunk = [&](int i) {
        const int k0 = i << 5;
        const int buf = i & 1;
        if (!(skipA0 && i == i0)) {
            #pragma unroll
            for (int it = 0; it < 4; it++) {
                const int sp  = it >> 1;
                const int idx = ((it & 1) << 8) + tid;
                const int r   = idx >> 2;
                const int c4  = idx & 3;
                const int gk  = k0 + (c4 << 3);
                const fp16* src = (gk < K1p) ? A1s[sp] + r * lda1 + gk
                                             : A2s[sp] + r * lda2 + (gk - K1p);
                CP16(sbase + sp * (2 * ASZ) + buf * ASZ + r * ARP + c4 * 16, src, 16);
            }
        }
        if (!(pre && i == i0)) {
            #pragma unroll
            for (int it = 0; it < 2; it++) {
                const int r   = tid >> 2;
                const int c4  = tid & 3;
                const int n   = n0 + r;
                const int nc  = (n < N) ? n : (N - 1);
                const fp16* src = Ws[it] + (long)nc * ldw + k0 + (c4 << 3);
                CP16(sbase + GBBASE + it * (2 * BSZ64) + buf * BSZ64 + r * ARP + c4 * 16,
                     src, (n < N) ? 16 : 0);
            }
        }
        CP_COMMIT();
    };

    if (i0 < i1) load_chunk(i0);
    for (int i = i0; i < i1; i++) {
        if (i + 1 < i1) { load_chunk(i + 1); CP_WAIT1(); }
        else            { CP_WAIT0(); }
        __syncthreads();
        const int buf = i & 1;

        #pragma unroll
        for (int ks = 0; ks < 2; ks++) {
            const uint32_t kb = (ks << 5) + ((lane & 3) << 2);
            uint32_t a[2][2][4];
            #pragma unroll
            for (int sp = 0; sp < 2; sp++)
                #pragma unroll
                for (int mt = 0; mt < 2; mt++) {
                    const char* base = sm + sp * (2 * ASZ) + buf * ASZ
                                     + (wm * 32 + mt * 16 + (lane >> 2)) * ARP + kb;
                    a[sp][mt][0] = *(const uint32_t*)(base);
                    a[sp][mt][1] = *(const uint32_t*)(base + 8 * ARP);
                    a[sp][mt][2] = *(const uint32_t*)(base + 16);
                    a[sp][mt][3] = *(const uint32_t*)(base + 8 * ARP + 16);
                }
            uint32_t b[2][NT][2];
            #pragma unroll
            for (int sp = 0; sp < 2; sp++)
                #pragma unroll
                for (int nt = 0; nt < NT; nt++) {
                    const char* base = sm + GBBASE + sp * (2 * BSZ64) + buf * BSZ64
                                     + (wn * 32 + nt * 8 + (lane >> 2)) * ARP + kb;
                    b[sp][nt][0] = *(const uint32_t*)(base);
                    b[sp][nt][1] = *(const uint32_t*)(base + 16);
                }
            #pragma unroll
            for (int mt = 0; mt < 2; mt++)
                #pragma unroll
                for (int nt = 0; nt < NT; nt++) {
                    mma_fp16(accs[mt][nt], a[0][mt], b[1][nt]);  // H*M (~2^-11)
                    mma_fp16(accs[mt][nt], a[1][mt], b[0][nt]);  // M*H (~2^-11)
                    float d[4] = {0.f, 0.f, 0.f, 0.f};           // H*H unchained
                    mma_fp16(d, a[0][mt], b[0][nt]);
                    acc[mt][nt][0] += d[0];
                    acc[mt][nt][1] += d[1];
                    acc[mt][nt][2] += d[2];
                    acc[mt][nt][3] += d[3];
                }
        }
        __syncthreads();
    }

    float* Cp = C + (size_t)kz * pstride;
    #pragma unroll
    for (int mt = 0; mt < 2; mt++) {
        int gm = wm * 32 + mt * 16 + (lane >> 2);
        #pragma unroll
        for (int nt = 0; nt < NT; nt++) {
            int gn = n0 + wn * 32 + nt * 8 + ((lane & 3) << 1);
            if (gn < N) {
                float r0 = acc[mt][nt][0] + accs[mt][nt][0];
                float r1 = acc[mt][nt][1] + accs[mt][nt][1];
                float r2 = acc[mt][nt][2] + accs[mt][nt][2];
                float r3 = acc[mt][nt][3] + accs[mt][nt][3];
                *(float2*)(Cp + (size_t)gm * ldc + gn)       = make_float2(r0, r1);
                *(float2*)(Cp + (size_t)(gm + 8) * ldc + gn) = make_float2(r2, r3);
            }
        }
    }
}

// ---------------------------------------------------------------------------
// Pointwise phase (own smem region at PWOFF; batched reductions).
// ---------------------------------------------------------------------------
__device__ __forceinline__ float sigm(float x) { return 1.0f / (1.0f + __expf(-x)); }

template <int NV>
__device__ __forceinline__ void blockReduceN(float* v, float* red) {
    const int lane = threadIdx.x & 31;
    const int w    = threadIdx.x >> 5;
    #pragma unroll
    for (int i = 0; i < NV; i++)
        #pragma unroll
        for (int o = 16; o > 0; o >>= 1) v[i] += __shfl_down_sync(0xffffffffu, v[i], o);
    if (lane == 0)
        #pragma unroll
        for (int i = 0; i < NV; i++) red[w * NV + i] = v[i];
    __syncthreads();
    if (threadIdx.x < NV) {
        float s = 0.0f;
        #pragma unroll
        for (int j = 0; j < 8; j++) s += red[j * NV + threadIdx.x];
        red[8 * NV + threadIdx.x] = s;
    }
    __syncthreads();
    #pragma unroll
    for (int i = 0; i < NV; i++) v[i] = red[8 * NV + i];
    __syncthreads();
}

template <int NP>
__device__ void pw_phase(char* smraw,
    const float* __restrict__ zp, int pstride,
    const float* __restrict__ bias,
    float* __restrict__ h, float* __restrict__ c, int H,
    const float* __restrict__ gg, const float* __restrict__ bg,
    const float* __restrict__ gc, const float* __restrict__ bc,
    fp16* __restrict__ sph, fp16* __restrict__ spm, int sp_lda,
    fp16* __restrict__ hih, int t)
{
    const int b = blockIdx.x;
    if (b >= B_) return;
    float* zs  = (float*)(smraw + PWOFF);
    float* red = zs + 4 * F_;
    const float invH = 1.0f / (float)H;
    const size_t rowoff = (size_t)b * 4 * H;

    float st[8] = {0, 0, 0, 0, 0, 0, 0, 0};
    for (int u = threadIdx.x; u < H; u += blockDim.x) {
        #pragma unroll
        for (int ch = 0; ch < 4; ch++) {
            const int off = ch * H + u;
            float v = bias[off];
            #pragma unroll
            for (int p = 0; p < NP; p++)
                v += __ldcg(zp + (size_t)p * pstride + rowoff + off);
            zs[off] = v;
            st[ch]     += v;
            st[4 + ch] += v * v;
        }
    }
    __syncthreads();
    blockReduceN<8>(st, red);

    float mu[4], rs[4];
    #pragma unroll
    for (int ch = 0; ch < 4; ch++) {
        mu[ch] = st[ch] * invH;
        float var = st[4 + ch] * invH - mu[ch] * mu[ch];
        rs[ch] = rsqrtf(var + 1e-5f);
    }

    float nc_r[3], so_r[3];
    float cst[2] = {0.0f, 0.0f};
    #pragma unroll
    for (int it = 0; it < 3; it++) {
        int u = threadIdx.x + it * 256;
        if (u < H) {
            float iv = (zs[0 * H + u] - mu[0]) * rs[0] * gg[0 * H + u] + bg[0 * H + u];
            float jv = (zs[1 * H + u] - mu[1]) * rs[1] * gg[1 * H + u] + bg[1 * H + u];
            float fv = (zs[2 * H + u] - mu[2]) * rs[2] * gg[2 * H + u] + bg[2 * H + u];
            float ov = (zs[3 * H + u] - mu[3]) * rs[3] * gg[3 * H + u] + bg[3 * H + u];
            float cold = c[(size_t)b * H + u];
            float nc = cold * sigm(fv + 1.0f) + sigm(iv) * tanhf(jv);
            nc_r[it] = nc;
            so_r[it] = sigm(ov);
            cst[0] += nc;
            cst[1] += nc * nc;
        }
    }
    blockReduceN<2>(cst, red);
    float muc = cst[0] * invH;
    float rsc = rsqrtf(cst[1] * invH - muc * muc + 1e-5f);

    #pragma unroll
    for (int it = 0; it < 3; it++) {
        int u = threadIdx.x + it * 256;
        if (u < H) {
            float nc = nc_r[it];
            float nh = tanhf((nc - muc) * rsc * gc[u] + bc[u]) * so_r[it];
            float hold = h[(size_t)b * H + u];
            float cold = c[(size_t)b * H + u];
            float hn = 0.9f * nh + 0.1f * hold;
            float cn = 0.5f * nc + 0.5f * cold;
            h[(size_t)b * H + u] = hn;
            c[(size_t)b * H + u] = cn;
            fp16 sh_, sm_;
            split2(hn, sh_, sm_);
            size_t so = (size_t)b * sp_lda + u;
            sph[so] = sh_; spm[so] = sm_;
            if (hih) hih[((size_t)b * T_ + t) * HI_LDA + u] = sh_;
        }
    }
}

// ---------------------------------------------------------------------------
// Persistent recurrence kernel: 100 steps x 6 phases + cross-phase prefetch.
// ---------------------------------------------------------------------------
struct RecParams {
    const fp16 *xh, *xm;
    const float *b0, *g0, *bg0, *gc0, *bc0;
    const float *bS, *gS, *bgS, *gcS, *bcS;
    const float *b1, *g1, *bg1, *gc1, *bc1;
    const fp16 *W0h, *W0m, *WSh, *WSm, *W1h, *W1m;
    float *fh, *fc, *sh, *sc, *z, *zS;
    fp16 *fhh, *fhm, *shh, *shm, *hih;
};

__global__ void __launch_bounds__(256)
rec_persist(RecParams P)
{
    extern __shared__ char sm[];
    unsigned mygen = 0;
    const int psC = B_ * 4 * F_;
    const int psS = B_ * 4 * S_;

    // Prefetch G0(t=0): B = W0 chunk i0; A (x region) for kz==0.
    prefetch_gemm(sm, P.xh, P.xm, T_ * E_, 128, P.fhh, P.fhm, FH_LDA,
                  P.W0h, P.W0m, 832, 832, 4 * F_, 44, KS_CELL, 0);

    for (int t = 0; t < T_; t++) {
        // Fast cell 0: A = [x_t | fh], Kpad=832, K1p=128 (prefetched)
        gemm_phase(sm, P.xh + t * E_, P.xm + t * E_, T_ * E_, 128,
                   P.fhh, P.fhm, FH_LDA,
                   P.W0h, P.W0m, 832,
                   P.z, 4 * F_, psC, 832, 4 * F_, 44, KS_CELL, 1, 0);
        // Prefetch GS: B = WS; A chunk for kz==4 lies in sh region (state of t-1).
        prefetch_gemm(sm, P.fhh, P.fhm, FH_LDA, 704, P.shh, P.shm, SH_LDA,
                      P.WSh, P.WSm, 1120, 1120, 4 * S_, 25, KS_SLOW, 4);
        gbar(mygen);
        pw_phase<KS_CELL>(sm, P.z, psC, P.b0, P.fh, P.fc, F_,
                          P.g0, P.bg0, P.gc0, P.bc0,
                          P.fhh, P.fhm, FH_LDA, nullptr, 0);
        gbar(mygen);

        // Slow cell: A = [fh | gap4 | sh], Kpad=1120, K1p=704 (prefetched)
        gemm_phase(sm, P.fhh, P.fhm, FH_LDA, 704,
                   P.shh, P.shm, SH_LDA,
                   P.WSh, P.WSm, 1120,
                   P.zS, 4 * S_, psS, 1120, 4 * S_, 25, KS_SLOW, 1, 4);
        // Prefetch G1: B = W1; A chunk for kz==2 lies in fh region (P0 done).
        prefetch_gemm(sm, P.shh, P.shm, SH_LDA, 400, P.fhh, P.fhm, FH_LDA,
                      P.W1h, P.W1m, 1120, 1120, 4 * F_, 44, KS_CELL, 2);
        gbar(mygen);
        pw_phase<KS_SLOW>(sm, P.zS, psS, P.bS, P.sh, P.sc, S_,
                          P.gS, P.bgS, P.gcS, P.bcS,
                          P.shh, P.shm, SH_LDA, nullptr, 0);
        gbar(mygen);

        // Fast cell 1: A = [sh | fh], Kpad=1120, K1p=400 (prefetched)
        gemm_phase(sm, P.shh, P.shm, SH_LDA, 400,
                   P.fhh, P.fhm, FH_LDA,
                   P.W1h, P.W1m, 1120,
                   P.z, 4 * F_, psC, 1120, 4 * F_, 44, KS_CELL, 1, 2);
        // Prefetch G0(t+1): B = W0; A chunk for kz==0 lies in x region.
        if (t + 1 < T_)
            prefetch_gemm(sm, P.xh + (t + 1) * E_, P.xm + (t + 1) * E_, T_ * E_, 128,
                          P.fhh, P.fhm, FH_LDA,
                          P.W0h, P.W0m, 832, 832, 4 * F_, 44, KS_CELL, 0);
        gbar(mygen);
        pw_phase<KS_CELL>(sm, P.z, psC, P.b1, P.fh, P.fc, F_,
                          P.g1, P.bg1, P.gc1, P.bc1,
                          P.fhh, P.fhm, FH_LDA, P.hih, t);
        gbar(mygen);
    }
}

// ---------------------------------------------------------------------------
// Projection GEMM (pure fp16 x1: round16(hist) @ round16(W)) — BN=128.
// ---------------------------------------------------------------------------
__global__ void __launch_bounds__(256)
gemm_proj(const fp16* __restrict__ Ah, long lda,
          const fp16* __restrict__ Wh, int ldw,
          const float* __restrict__ bias,
          float* __restrict__ C, long ldc, int N, int Kpad)
{
    constexpr int NT  = 8;
    constexpr int BSZ = 128 * ARP;            // 10240
    constexpr uint32_t BBASE = 2 * ASZ;       // 20480

    extern __shared__ char sm[];
    const uint32_t sbase = smem_u32(sm);
    const int tid  = threadIdx.x;
    const int wid  = tid >> 5;
    const int lane = tid & 31;
    const int wm   = wid & 3;
    const int wn   = wid >> 2;
    const int n0   = blockIdx.x * 128;
    const long m0  = (long)blockIdx.y * 128;
    const int nk   = Kpad >> 5;

    float acc[2][NT][4];
    #pragma unroll
    for (int mt = 0; mt < 2; mt++)
        #pragma unroll
        for (int nt = 0; nt < NT; nt++)
            #pragma unroll
            for (int r = 0; r < 4; r++) acc[mt][nt][r] = 0.0f;

    auto load_chunk = [&](int i) {
        const int k0 = i << 5;
        const int buf = i & 1;
        #pragma unroll
        for (int it = 0; it < 2; it++) {
            const int idx = (it << 8) + tid;
            const int r   = idx >> 2;
            const int c4  = idx & 3;
            CP16(sbase + buf * ASZ + r * ARP + c4 * 16,
                 Ah + (m0 + r) * lda + k0 + (c4 << 3), 16);
        }
        #pragma unroll
        for (int it = 0; it < 2; it++) {
            const int idx = (it << 8) + tid;
            const int r   = idx >> 2;
            const int c4  = idx & 3;
            const int n   = n0 + r;
            const int nc  = (n < N) ? n : (N - 1);
            CP16(sbase + BBASE + buf * BSZ + r * ARP + c4 * 16,
                 Wh + (long)nc * ldw + k0 + (c4 << 3), (n < N) ? 16 : 0);
        }
        CP_COMMIT();
    };

    load_chunk(0);
    for (int i = 0; i < nk; i++) {
        if (i + 1 < nk) { load_chunk(i + 1); CP_WAIT1(); }
        else            { CP_WAIT0(); }
        __syncthreads();
        const int buf = i & 1;

        #pragma unroll
        for (int ks = 0; ks < 2; ks++) {
            const uint32_t kb = (ks << 5) + ((lane & 3) << 2);
            uint32_t a[2][4];
            #pragma unroll
            for (int mt = 0; mt < 2; mt++) {
                const char* base = sm + buf * ASZ
                                 + (wm * 32 + mt * 16 + (lane >> 2)) * ARP + kb;
                a[mt][0] = *(const uint32_t*)(base);
                a[mt][1] = *(const uint32_t*)(base + 8 * ARP);
                a[mt][2] = *(const uint32_t*)(base + 16);
                a[mt][3] = *(const uint32_t*)(base + 8 * ARP + 16);
            }
            uint32_t b[NT][2];
            #pragma unroll
            for (int nt = 0; nt < NT; nt++) {
                const char* base = sm + BBASE + buf * BSZ
                                 + (wn * 64 + nt * 8 + (lane >> 2)) * ARP + kb;
                b[nt][0] = *(const uint32_t*)(base);
                b[nt][1] = *(const uint32_t*)(base + 16);
            }
            #pragma unroll
            for (int mt = 0; mt < 2; mt++)
                #pragma unroll
                for (int nt = 0; nt < NT; nt++)
                    mma_fp16(acc[mt][nt], a[mt], b[nt]);
        }
        __syncthreads();
    }

    #pragma unroll
    for (int mt = 0; mt < 2; mt++) {
        long gm = m0 + wm * 32 + mt * 16 + (lane >> 2);
        #pragma unroll
        for (int nt = 0; nt < NT; nt++) {
            int gn = n0 + wn * 64 + nt * 8 + ((lane & 3) << 1);
            if (gn < N) {
                float2 bv = *(const float2*)(bias + gn);
                *(float2*)(C + gm * ldc + gn) =
                    make_float2(acc[mt][nt][0] + bv.x, acc[mt][nt][1] + bv.y);
                *(float2*)(C + (gm + 8) * ldc + gn) =
                    make_float2(acc[mt][nt][2] + bv.x, acc[mt][nt][3] + bv.y);
            }
        }
    }
}

// ---------------------------------------------------------------------------
// Single fused setup kernel: weight transposes+splits, input split, state init.
// ---------------------------------------------------------------------------
__global__ void setup_all(const float* __restrict__ W0, const float* __restrict__ WS,
                          const float* __restrict__ W1, const float* __restrict__ Wout,
                          const float* __restrict__ inputs)
{
    const long i0 = (long)blockIdx.x * blockDim.x + threadIdx.x;
    const long gsz = (long)gridDim.x * blockDim.x;
    const fp16 hz = __float2half(0.0f);

    // W0: [828, 2800] -> K-major [2800, 832]
    for (long i = i0; i < 2800L * 832; i += gsz) {
        int n = (int)(i / 832), k = (int)(i % 832);
        float v = (k < 828) ? W0[(long)k * 2800 + n] : 0.0f;
        split2(v, g_W0h[i], g_W0m[i]);
    }
    // WS: [1100, 1600] -> [1600, 1120] with 4-gap at 700
    for (long i = i0; i < 1600L * 1120; i += gsz) {
        int n = (int)(i / 1120), k = (int)(i % 1120);
        float v = 0.0f;
        if (k < 700)                       v = WS[(long)k * 1600 + n];
        else if (k >= 704 && k < 1104)     v = WS[(long)(k - 4) * 1600 + n];
        split2(v, g_WSh[i], g_WSm[i]);
    }
    // W1: [1100, 2800] -> [2800, 1120]
    for (long i = i0; i < 2800L * 1120; i += gsz) {
        int n = (int)(i / 1120), k = (int)(i % 1120);
        float v = (k < 1100) ? W1[(long)k * 2800 + n] : 0.0f;
        split2(v, g_W1h[i], g_W1m[i]);
    }
    // Wout: [700, 10000] -> [10000, 704], high split only
    for (long i = i0; i < 10000L * 704; i += gsz) {
        int n = (int)(i / 704), k = (int)(i % 704);
        float v = (k < 700) ? Wout[(long)k * 10000 + n] : 0.0f;
        g_Woh[i] = __float2half_rn(v);
    }
    // inputs split
    for (long i = i0; i < (long)B_ * T_ * E_; i += gsz) {
        fp16 h, m;
        split2(inputs[i], h, m);
        g_xh[i] = h; g_xm[i] = m;
    }
    // states + barrier state
    if (i0 == 0) g_bargen = 0u;
    for (long j = i0; j < GRID_P * 8; j += gsz) g_flags[j] = 0u;
    for (long j = i0; j < B_ * F_; j += gsz) { g_fh[j] = 0.0f; g_fc[j] = 0.0f; }
    for (long j = i0; j < B_ * S_; j += gsz) { g_sh[j] = 0.0f; g_sc[j] = 0.0f; }
    for (long j = i0; j < B_ * FH_LDA; j += gsz) { g_fhh[j] = hz; g_fhm[j] = hz; }
    for (long j = i0; j < B_ * SH_LDA; j += gsz) { g_shh[j] = hz; g_shm[j] = hz; }
    for (long j = i0; j < B_ * T_ * 4; j += gsz) {
        size_t off = (size_t)(j >> 2) * HI_LDA + F_ + (j & 3);
        g_hih[off] = hz;
    }
}

__global__ void tail_copy(float* __restrict__ out, size_t out_total)
{
    int i = blockIdx.x * blockDim.x + threadIdx.x;
    const size_t base = (size_t)B_ * T_ * V_;
    const int nF = B_ * F_, nS = B_ * S_;
    const int total = 2 * nF + 2 * nS;
    if (i >= total) return;
    float v;
    size_t off = base + i;
    if (i < nF)               v = g_fh[i];
    else if (i < 2 * nF)      v = g_fc[i - nF];
    else if (i < 2 * nF + nS) v = g_sh[i - 2 * nF];
    else                      v = g_sc[i - 2 * nF - nS];
    if (off < out_total) out[off] = v;
}

// ---------------------------------------------------------------------------
// Launch
// ---------------------------------------------------------------------------
extern "C" void kernel_launch(void* const* d_in, const int* in_sizes, int n_in,
                              void* d_out, int out_size)
{
    const float* inputs = (const float*)d_in[0];
    const float* W0  = (const float*)d_in[1];
    const float* b0  = (const float*)d_in[2];
    const float* g0  = (const float*)d_in[3];
    const float* bg0 = (const float*)d_in[4];
    const float* gc0 = (const float*)d_in[5];
    const float* bc0 = (const float*)d_in[6];
    const float* W1  = (const float*)d_in[7];
    const float* b1  = (const float*)d_in[8];
    const float* g1  = (const float*)d_in[9];
    const float* bg1 = (const float*)d_in[10];
    const float* gc1 = (const float*)d_in[11];
    const float* bc1 = (const float*)d_in[12];
    const float* WS  = (const float*)d_in[13];
    const float* bS  = (const float*)d_in[14];
    const float* gS  = (const float*)d_in[15];
    const float* bgS = (const float*)d_in[16];
    const float* gcS = (const float*)d_in[17];
    const float* bcS = (const float*)d_in[18];
    const float* Wout = (const float*)d_in[19];
    const float* bout = (const float*)d_in[20];
    float* out = (float*)d_out;

    RecParams P;
    float *z, *zS;
    fp16 *Woh, *hih;
    cudaGetSymbolAddress((void**)&P.fh,  g_fh);  cudaGetSymbolAddress((void**)&P.fc,  g_fc);
    cudaGetSymbolAddress((void**)&P.sh,  g_sh);  cudaGetSymbolAddress((void**)&P.sc,  g_sc);
    cudaGetSymbolAddress((void**)&z,     g_z);   cudaGetSymbolAddress((void**)&zS,    g_zS);
    cudaGetSymbolAddress((void**)&P.xh,  g_xh);  cudaGetSymbolAddress((void**)&P.xm,  g_xm);
    cudaGetSymbolAddress((void**)&P.fhh, g_fhh); cudaGetSymbolAddress((void**)&P.fhm, g_fhm);
    cudaGetSymbolAddress((void**)&P.shh, g_shh); cudaGetSymbolAddress((void**)&P.shm, g_shm);
    cudaGetSymbolAddress((void**)&hih,   g_hih);
    cudaGetSymbolAddress((void**)&P.W0h, g_W0h); cudaGetSymbolAddress((void**)&P.W0m, g_W0m);
    cudaGetSymbolAddress((void**)&P.WSh, g_WSh); cudaGetSymbolAddress((void**)&P.WSm, g_WSm);
    cudaGetSymbolAddress((void**)&P.W1h, g_W1h); cudaGetSymbolAddress((void**)&P.W1m, g_W1m);
    cudaGetSymbolAddress((void**)&Woh,   g_Woh);
    P.z = z; P.zS = zS;
    P.hih = hih;
    P.b0 = b0; P.g0 = g0; P.bg0 = bg0; P.gc0 = gc0; P.bc0 = bc0;
    P.b1 = b1; P.g1 = g1; P.bg1 = bg1; P.gc1 = gc1; P.bc1 = bc1;
    P.bS = bS; P.gS = gS; P.bgS = bgS; P.gcS = gcS; P.bcS = bcS;

    const int SMPR = 2 * ASZ + 2 * (128 * ARP);   // 40960 (projection)
    cudaFuncSetAttribute(rec_persist, cudaFuncAttributeMaxDynamicSharedMemorySize, SMP);
    cudaFuncSetAttribute(gemm_proj,   cudaFuncAttributeMaxDynamicSharedMemorySize, SMPR);

    // One fused setup launch
    setup_all<<<1024, 256>>>(W0, WS, W1, Wout, inputs);

    // Entire recurrence: ONE persistent kernel
    rec_persist<<<GRID_P, 256, SMP>>>(P);

    // Output projection: round16(hist)[12800,704] @ round16(Wout) + bias
    {
        const dim3 grid((V_ + 127) / 128, (B_ * T_) / 128, 1);   // 79 x 100
        gemm_proj<<<grid, 256, SMPR>>>(
            hih, HI_LDA, Woh, 704, bout, out, V_, V_, 704);
    }

    {
        int total = 2 * B_ * F_ + 2 * B_ * S_;
        tail_copy<<<(total + 255) / 256, 256>>>(out, (size_t)out_size);
    }
}

// round 16
// speedup vs baseline: 1.0029x; 1.0029x over previous
#include <cuda_runtime.h>
#include <cuda_fp16.h>
#include <cstdint>

// Problem constants
#define B_  128
#define T_  100
#define E_  128
#define F_  700
#define S_  400
#define V_  10000

#define FH_LDA 720
#define SH_LDA 424
#define HI_LDA 704

#define KS_CELL 3
#define KS_SLOW 5
#define GRID_P  132          // recurrence CTAs (44*3)
#define GRID_ALL 148         // + 16 projection workers
#define NTILES_T 79          // ceil(10000/128)

typedef __half fp16;

// ---------------------------------------------------------------------------
// Static device scratch
// ---------------------------------------------------------------------------
__device__ float g_fh[B_ * F_];
__device__ float g_fc[B_ * F_];
__device__ float g_sh[B_ * S_];
__device__ float g_sc[B_ * S_];
__device__ float g_z [KS_CELL * B_ * 4 * F_];
__device__ float g_zS[KS_SLOW * B_ * 4 * S_];

__device__ fp16 g_xh[B_ * T_ * E_], g_xm[B_ * T_ * E_];
__device__ fp16 g_fhh[B_ * FH_LDA], g_fhm[B_ * FH_LDA];
__device__ fp16 g_shh[B_ * SH_LDA], g_shm[B_ * SH_LDA];
__device__ fp16 g_hih[(size_t)B_ * T_ * HI_LDA];          // T-MAJOR: row = t*B + b

__device__ fp16 g_W0h[(size_t)4 * F_ * 832],  g_W0m[(size_t)4 * F_ * 832];
__device__ fp16 g_WSh[(size_t)4 * S_ * 1120], g_WSm[(size_t)4 * S_ * 1120];
__device__ fp16 g_W1h[(size_t)4 * F_ * 1120], g_W1m[(size_t)4 * F_ * 1120];
__device__ fp16 g_Woh[(size_t)V_ * 704];

// Grid barrier + projection ticket state
__device__ unsigned g_flags[GRID_P * 8];
__device__ unsigned g_bargen;
__device__ unsigned g_ptk;

// ---------------------------------------------------------------------------
// Helpers
// ---------------------------------------------------------------------------
__device__ __forceinline__ uint32_t smem_u32(const void* p) {
    uint32_t a;
    asm("{ .reg .u64 t; cvta.to.shared.u64 t, %1; cvt.u32.u64 %0, t; }" : "=r"(a) : "l"(p));
    return a;
}
__device__ __forceinline__ void split2(float x, fp16& h, fp16& m) {
    h = __float2half_rn(x);
    m = __float2half_rn(x - __half2float(h));
}
__device__ __forceinline__ void mma_fp16(float c[4], const uint32_t a[4], const uint32_t b[2]) {
    asm volatile("mma.sync.aligned.m16n8k16.row.col.f32.f16.f16.f32 "
                 "{%0,%1,%2,%3}, {%4,%5,%6,%7}, {%8,%9}, {%0,%1,%2,%3};"
                 : "+f"(c[0]), "+f"(c[1]), "+f"(c[2]), "+f"(c[3])
                 : "r"(a[0]), "r"(a[1]), "r"(a[2]), "r"(a[3]), "r"(b[0]), "r"(b[1]));
}
#define CP16(dst, src, sz) \
    asm volatile("cp.async.cg.shared.global [%0], [%1], 16, %2;" \
                 :: "r"(dst), "l"(src), "r"(sz))
#define CP_COMMIT() asm volatile("cp.async.commit_group;" ::: "memory")
#define CP_WAIT1()  asm volatile("cp.async.wait_group 1;" ::: "memory")
#define CP_WAIT0()  asm volatile("cp.async.wait_group 0;" ::: "memory")

#define ARP    80
#define ASZ    (128 * ARP)           // 10240
#define BSZ64  (64 * ARP)            // 5120
#define BSZ128 (128 * ARP)           // 10240
#define GBBASE (4 * ASZ)             // 40960: B base, recurrence GEMM
#define SMP    (4 * ASZ + 4 * BSZ64) // 61440 total dynamic smem

// ---------------------------------------------------------------------------
// Fast grid barrier (132 rec CTAs only; workers never call this).
// ---------------------------------------------------------------------------
__device__ __forceinline__ void gbar(unsigned& mygen) {
    mygen++;
    __syncthreads();
    __threadfence();
    if (threadIdx.x == 0)
        *((volatile unsigned*)&g_flags[blockIdx.x * 8]) = mygen;
    if (blockIdx.x == 0) {
        if (threadIdx.x < GRID_P) {
            volatile unsigned* f = &g_flags[threadIdx.x * 8];
            while (*f < mygen) {}
        }
        __syncthreads();
        if (threadIdx.x == 0) {
            __threadfence();
            *((volatile unsigned*)&g_bargen) = mygen;
        }
    } else {
        if (threadIdx.x == 0) {
            volatile unsigned* g = &g_bargen;
            while (*g < mygen) {}
        }
    }
    __syncthreads();
    __threadfence();
}

// ---------------------------------------------------------------------------
// Recurrence GEMM phase: fp16 2-way split, 3 products.
// ---------------------------------------------------------------------------
__device__ void gemm_phase(char* sm,
    const fp16* __restrict__ A1h, const fp16* __restrict__ A1m,
    int lda1, int K1p,
    const fp16* __restrict__ A2h, const fp16* __restrict__ A2m,
    int lda2,
    const fp16* __restrict__ Wh, const fp16* __restrict__ Wm,
    int ldw,
    float* __restrict__ C, int ldc, int pstride,
    int Kpad, int N, int tnc, int KS)
{
    constexpr int NT = 4;

    const int cta = blockIdx.x;
    if (cta >= tnc * KS) return;

    const uint32_t sbase = smem_u32(sm);
    const int tid  = threadIdx.x;
    const int wid  = tid >> 5;
    const int lane = tid & 31;
    const int wm   = wid & 3;
    const int wn   = wid >> 2;
    const int n0   = (cta % tnc) * 64;
    const int kz   = cta / tnc;
    const int nk   = Kpad >> 5;
    const int nkq  = (nk + KS - 1) / KS;
    const int i0   = kz * nkq;
    const int i1   = (i0 + nkq < nk) ? (i0 + nkq) : nk;

    const fp16* A1s[2] = {A1h, A1m};
    const fp16* A2s[2] = {A2h, A2m};
    const fp16* Ws [2] = {Wh,  Wm};

    float acc[2][NT][4], accs[2][NT][4];
    #pragma unroll
    for (int mt = 0; mt < 2; mt++)
        #pragma unroll
        for (int nt = 0; nt < NT; nt++)
            #pragma unroll
            for (int r = 0; r < 4; r++) { acc[mt][nt][r] = 0.0f; accs[mt][nt][r] = 0.0f; }

    auto load_chunk = [&](int i) {
        const int k0 = i << 5;
        const int buf = i & 1;
        #pragma unroll
        for (int it = 0; it < 4; it++) {
            const int sp  = it >> 1;
            const int idx = ((it & 1) << 8) + tid;
            const int r   = idx >> 2;
            const int c4  = idx & 3;
            const int gk  = k0 + (c4 << 3);
            const fp16* src = (gk < K1p) ? A1s[sp] + r * lda1 + gk
                                         : A2s[sp] + r * lda2 + (gk - K1p);
            CP16(sbase + sp * (2 * ASZ) + buf * ASZ + r * ARP + c4 * 16, src, 16);
        }
        #pragma unroll
        for (int it = 0; it < 2; it++) {
            const int r   = tid >> 2;
            const int c4  = tid & 3;
            const int n   = n0 + r;
            const int nc  = (n < N) ? n : (N - 1);
            const fp16* src = Ws[it] + (long)nc * ldw + k0 + (c4 << 3);
            CP16(sbase + GBBASE + it * (2 * BSZ64) + buf * BSZ64 + r * ARP + c4 * 16,
                 src, (n < N) ? 16 : 0);
        }
        CP_COMMIT();
    };

    if (i0 < i1) load_chunk(i0);
    for (int i = i0; i < i1; i++) {
        if (i + 1 < i1) { load_chunk(i + 1); CP_WAIT1(); }
        else            { CP_WAIT0(); }
        __syncthreads();
        const int buf = i & 1;

        #pragma unroll
        for (int ks = 0; ks < 2; ks++) {
            const uint32_t kb = (ks << 5) + ((lane & 3) << 2);
            uint32_t a[2][2][4];
            #pragma unroll
            for (int sp = 0; sp < 2; sp++)
                #pragma unroll
                for (int mt = 0; mt < 2; mt++) {
                    const char* base = sm + sp * (2 * ASZ) + buf * ASZ
                                     + (wm * 32 + mt * 16 + (lane >> 2)) * ARP + kb;
                    a[sp][mt][0] = *(const uint32_t*)(base);
                    a[sp][mt][1] = *(const uint32_t*)(base + 8 * ARP);
                    a[sp][mt][2] = *(const uint32_t*)(base + 16);
                    a[sp][mt][3] = *(const uint32_t*)(base + 8 * ARP + 16);
                }
            uint32_t b[2][NT][2];
            #pragma unroll
            for (int sp = 0; sp < 2; sp++)
                #pragma unroll
                for (int nt = 0; nt < NT; nt++) {
                    const char* base = sm + GBBASE + sp * (2 * BSZ64) + buf * BSZ64
                                     + (wn * 32 + nt * 8 + (lane >> 2)) * ARP + kb;
                    b[sp][nt][0] = *(const uint32_t*)(base);
                    b[sp][nt][1] = *(const uint32_t*)(base + 16);
                }
            #pragma unroll
            for (int mt = 0; mt < 2; mt++)
                #pragma unroll
                for (int nt = 0; nt < NT; nt++) {
                    mma_fp16(accs[mt][nt], a[0][mt], b[1][nt]);  // H*M (~2^-11)
                    mma_fp16(accs[mt][nt], a[1][mt], b[0][nt]);  // M*H (~2^-11)
                    float d[4] = {0.f, 0.f, 0.f, 0.f};           // H*H unchained
                    mma_fp16(d, a[0][mt], b[0][nt]);
                    acc[mt][nt][0] += d[0];
                    acc[mt][nt][1] += d[1];
                    acc[mt][nt][2] += d[2];
                    acc[mt][nt][3] += d[3];
                }
        }
        __syncthreads();
    }

    float* Cp = C + (size_t)kz * pstride;
    #pragma unroll
    for (int mt = 0; mt < 2; mt++) {
        int gm = wm * 32 + mt * 16 + (lane >> 2);
        #pragma unroll
        for (int nt = 0; nt < NT; nt++) {
            int gn = n0 + wn * 32 + nt * 8 + ((lane & 3) << 1);
            if (gn < N) {
                float r0 = acc[mt][nt][0] + accs[mt][nt][0];
                float r1 = acc[mt][nt][1] + accs[mt][nt][1];
                float r2 = acc[mt][nt][2] + accs[mt][nt][2];
                float r3 = acc[mt][nt][3] + accs[mt][nt][3];
                *(float2*)(Cp + (size_t)gm * ldc + gn)       = make_float2(r0, r1);
                *(float2*)(Cp + (size_t)(gm + 8) * ldc + gn) = make_float2(r2, r3);
            }
        }
    }
}

// ---------------------------------------------------------------------------
// Pointwise phase (zs at smem base; batched reductions). hist write T-MAJOR.
// ---------------------------------------------------------------------------
__device__ __forceinline__ float sigm(float x) { return 1.0f / (1.0f + __expf(-x)); }

template <int NV>
__device__ __forceinline__ void blockReduceN(float* v, float* red) {
    const int lane = threadIdx.x & 31;
    const int w    = threadIdx.x >> 5;
    #pragma unroll
    for (int i = 0; i < NV; i++)
        #pragma unroll
        for (int o = 16; o > 0; o >>= 1) v[i] += __shfl_down_sync(0xffffffffu, v[i], o);
    if (lane == 0)
        #pragma unroll
        for (int i = 0; i < NV; i++) red[w * NV + i] = v[i];
    __syncthreads();
    if (threadIdx.x < NV) {
        float s = 0.0f;
        #pragma unroll
        for (int j = 0; j < 8; j++) s += red[j * NV + threadIdx.x];
        red[8 * NV + threadIdx.x] = s;
    }
    __syncthreads();
    #pragma unroll
    for (int i = 0; i < NV; i++) v[i] = red[8 * NV + i];
    __syncthreads();
}

template <int NP>
__device__ void pw_phase(char* smraw,
    const float* __restrict__ zp, int pstride,
    const float* __restrict__ bias,
    float* __restrict__ h, float* __restrict__ c, int H,
    const float* __restrict__ gg, const float* __restrict__ bg,
    const float* __restrict__ gc, const float* __restrict__ bc,
    fp16* __restrict__ sph, fp16* __restrict__ spm, int sp_lda,
    fp16* __restrict__ hih, int t)
{
    const int b = blockIdx.x;
    if (b >= B_) return;
    float* zs  = (float*)smraw;
    float* red = zs + 4 * F_;
    const float invH = 1.0f / (float)H;
    const size_t rowoff = (size_t)b * 4 * H;

    float st[8] = {0, 0, 0, 0, 0, 0, 0, 0};
    for (int u = threadIdx.x; u < H; u += blockDim.x) {
        #pragma unroll
        for (int ch = 0; ch < 4; ch++) {
            const int off = ch * H + u;
            float v = bias[off];
            #pragma unroll
            for (int p = 0; p < NP; p++)
                v += __ldcg(zp + (size_t)p * pstride + rowoff + off);
            zs[off] = v;
            st[ch]     += v;
            st[4 + ch] += v * v;
        }
    }
    __syncthreads();
    blockReduceN<8>(st, red);

    float mu[4], rs[4];
    #pragma unroll
    for (int ch = 0; ch < 4; ch++) {
        mu[ch] = st[ch] * invH;
        float var = st[4 + ch] * invH - mu[ch] * mu[ch];
        rs[ch] = rsqrtf(var + 1e-5f);
    }

    float nc_r[3], so_r[3];
    float cst[2] = {0.0f, 0.0f};
    #pragma unroll
    for (int it = 0; it < 3; it++) {
        int u = threadIdx.x + it * 256;
        if (u < H) {
            float iv = (zs[0 * H + u] - mu[0]) * rs[0] * gg[0 * H + u] + bg[0 * H + u];
            float jv = (zs[1 * H + u] - mu[1]) * rs[1] * gg[1 * H + u] + bg[1 * H + u];
            float fv = (zs[2 * H + u] - mu[2]) * rs[2] * gg[2 * H + u] + bg[2 * H + u];
            float ov = (zs[3 * H + u] - mu[3]) * rs[3] * gg[3 * H + u] + bg[3 * H + u];
            float cold = c[(size_t)b * H + u];
            float nc = cold * sigm(fv + 1.0f) + sigm(iv) * tanhf(jv);
            nc_r[it] = nc;
            so_r[it] = sigm(ov);
            cst[0] += nc;
            cst[1] += nc * nc;
        }
    }
    blockReduceN<2>(cst, red);
    float muc = cst[0] * invH;
    float rsc = rsqrtf(cst[1] * invH - muc * muc + 1e-5f);

    #pragma unroll
    for (int it = 0; it < 3; it++) {
        int u = threadIdx.x + it * 256;
        if (u < H) {
            float nc = nc_r[it];
            float nh = tanhf((nc - muc) * rsc * gc[u] + bc[u]) * so_r[it];
            float hold = h[(size_t)b * H + u];
            float cold = c[(size_t)b * H + u];
            float hn = 0.9f * nh + 0.1f * hold;
            float cn = 0.5f * nc + 0.5f * cold;
            h[(size_t)b * H + u] = hn;
            c[(size_t)b * H + u] = cn;
            fp16 sh_, sm_;
            split2(hn, sh_, sm_);
            size_t so = (size_t)b * sp_lda + u;
            sph[so] = sh_; spm[so] = sm_;
            if (hih) hih[((size_t)t * B_ + b) * HI_LDA + u] = sh_;   // T-MAJOR
        }
    }
}

// ---------------------------------------------------------------------------
// Projection tile (device fn): one timestep t (M=128 rows, t-major hist) x
// one 128-col N-tile. Pure fp16 x1. Writes PERMUTED output rows b*T + t.
// SMEM: A @ [0, 2*ASZ), B @ [2*ASZ, 2*ASZ + 2*BSZ128).
// ---------------------------------------------------------------------------
__device__ void proj_tile(char* sm, int t, int nI,
    const fp16* __restrict__ Ah, const fp16* __restrict__ Wh,
    const float* __restrict__ bias, float* __restrict__ out)
{
    constexpr int NT = 8;
    constexpr uint32_t BB = 2 * ASZ;

    const uint32_t sbase = smem_u32(sm);
    const int tid  = threadIdx.x;
    const int wid  = tid >> 5;
    const int lane = tid & 31;
    const int wm   = wid & 3;
    const int wn   = wid >> 2;
    const int n0   = nI * 128;
    const long m0  = (long)t * 128;        // hist rows for timestep t
    const int nk   = 704 >> 5;             // 22

    float acc[2][NT][4];
    #pragma unroll
    for (int mt = 0; mt < 2; mt++)
        #pragma unroll
        for (int nt = 0; nt < NT; nt++)
            #pragma unroll
            for (int r = 0; r < 4; r++) acc[mt][nt][r] = 0.0f;

    auto load_chunk = [&](int i) {
        const int k0 = i << 5;
        const int buf = i & 1;
        #pragma unroll
        for (int it = 0; it < 2; it++) {
            const int idx = (it << 8) + tid;
            const int r   = idx >> 2;
            const int c4  = idx & 3;
            CP16(sbase + buf * ASZ + r * ARP + c4 * 16,
                 Ah + (m0 + r) * HI_LDA + k0 + (c4 << 3), 16);
        }
        #pragma unroll
        for (int it = 0; it < 2; it++) {
            const int idx = (it << 8) + tid;
            const int r   = idx >> 2;
            const int c4  = idx & 3;
            const int n   = n0 + r;
            const int nc  = (n < V_) ? n : (V_ - 1);
            CP16(sbase + BB + buf * BSZ128 + r * ARP + c4 * 16,
                 Wh + (long)nc * 704 + k0 + (c4 << 3), (n < V_) ? 16 : 0);
        }
        CP_COMMIT();
    };

    load_chunk(0);
    for (int i = 0; i < nk; i++) {
        if (i + 1 < nk) { load_chunk(i + 1); CP_WAIT1(); }
        else            { CP_WAIT0(); }
        __syncthreads();
        const int buf = i & 1;

        #pragma unroll
        for (int ks = 0; ks < 2; ks++) {
            const uint32_t kb = (ks << 5) + ((lane & 3) << 2);
            uint32_t a[2][4];
            #pragma unroll
            for (int mt = 0; mt < 2; mt++) {
                const char* base = sm + buf * ASZ
                                 + (wm * 32 + mt * 16 + (lane >> 2)) * ARP + kb;
                a[mt][0] = *(const uint32_t*)(base);
                a[mt][1] = *(const uint32_t*)(base + 8 * ARP);
                a[mt][2] = *(const uint32_t*)(base + 16);
                a[mt][3] = *(const uint32_t*)(base + 8 * ARP + 16);
            }
            uint32_t b[NT][2];
            #pragma unroll
            for (int nt = 0; nt < NT; nt++) {
                const char* base = sm + BB + buf * BSZ128
                                 + (wn * 64 + nt * 8 + (lane >> 2)) * ARP + kb;
                b[nt][0] = *(const uint32_t*)(base);
                b[nt][1] = *(const uint32_t*)(base + 16);
            }
            #pragma unroll
            for (int mt = 0; mt < 2; mt++)
                #pragma unroll
                for (int nt = 0; nt < NT; nt++)
                    mma_fp16(acc[mt][nt], a[mt], b[nt]);
        }
        __syncthreads();
    }

    #pragma unroll
    for (int mt = 0; mt < 2; mt++) {
        int b0 = wm * 32 + mt * 16 + (lane >> 2);          // batch index (row in tile)
        long or0 = (long)b0 * T_ + t;                       // permuted output rows
        long or1 = (long)(b0 + 8) * T_ + t;
        #pragma unroll
        for (int nt = 0; nt < NT; nt++) {
            int gn = n0 + wn * 64 + nt * 8 + ((lane & 3) << 1);
            if (gn < V_) {
                float2 bv = *(const float2*)(bias + gn);
                *(float2*)(out + or0 * V_ + gn) =
                    make_float2(acc[mt][nt][0] + bv.x, acc[mt][nt][1] + bv.y);
                *(float2*)(out + or1 * V_ + gn) =
                    make_float2(acc[mt][nt][2] + bv.x, acc[mt][nt][3] + bv.y);
            }
        }
    }
}

// Ticket loop: grab tile, wait for its timestep to complete, compute.
__device__ void proj_loop(char* sm,
    const fp16* __restrict__ Ah, const fp16* __restrict__ Wh,
    const float* __restrict__ bias, float* __restrict__ out)
{
    __shared__ unsigned s_tk;
    while (true) {
        if (threadIdx.x == 0) s_tk = atomicAdd(&g_ptk, 1u);
        __syncthreads();
        unsigned tk = s_tk;
        __syncthreads();
        if (tk >= (unsigned)(T_ * NTILES_T)) break;
        const int t  = (int)(tk / NTILES_T);
        const int nI = (int)(tk % NTILES_T);
        if (threadIdx.x == 0) {
            volatile unsigned* g = &g_bargen;
            while (*g < 6u * (unsigned)(t + 1)) __nanosleep(256);
        }
        __syncthreads();
        __threadfence();
        proj_tile(sm, t, nI, Ah, Wh, bias, out);
        __syncthreads();
    }
}

// ---------------------------------------------------------------------------
// Persistent kernel: 132 rec CTAs (6 phases x 100 steps) + 16 proj workers;
// rec CTAs join the projection ticket queue when the recurrence finishes.
// ---------------------------------------------------------------------------
struct RecParams {
    const fp16 *xh, *xm;
    const float *b0, *g0, *bg0, *gc0, *bc0;
    const float *bS, *gS, *bgS, *gcS, *bcS;
    const float *b1, *g1, *bg1, *gc1, *bc1;
    const fp16 *W0h, *W0m, *WSh, *WSm, *W1h, *W1m;
    float *fh, *fc, *sh, *sc, *z, *zS;
    fp16 *fhh, *fhm, *shh, *shm, *hih;
    const fp16 *Woh;
    const float *bout;
    float *out;
};

__global__ void __launch_bounds__(256)
rec_persist(RecParams P)
{
    extern __shared__ char sm[];

    if (blockIdx.x >= GRID_P) {             // projection worker CTA
        proj_loop(sm, P.hih, P.Woh, P.bout, P.out);
        return;
    }

    unsigned mygen = 0;
    const int psC = B_ * 4 * F_;
    const int psS = B_ * 4 * S_;

    for (int t = 0; t < T_; t++) {
        gemm_phase(sm, P.xh + t * E_, P.xm + t * E_, T_ * E_, 128,
                   P.fhh, P.fhm, FH_LDA,
                   P.W0h, P.W0m, 832,
                   P.z, 4 * F_, psC, 832, 4 * F_, 44, KS_CELL);
        gbar(mygen);
        pw_phase<KS_CELL>(sm, P.z, psC, P.b0, P.fh, P.fc, F_,
                          P.g0, P.bg0, P.gc0, P.bc0,
                          P.fhh, P.fhm, FH_LDA, nullptr, 0);
        gbar(mygen);

        gemm_phase(sm, P.fhh, P.fhm, FH_LDA, 704,
                   P.shh, P.shm, SH_LDA,
                   P.WSh, P.WSm, 1120,
                   P.zS, 4 * S_, psS, 1120, 4 * S_, 25, KS_SLOW);
        gbar(mygen);
        pw_phase<KS_SLOW>(sm, P.zS, psS, P.bS, P.sh, P.sc, S_,
                          P.gS, P.bgS, P.gcS, P.bcS,
                          P.shh, P.shm, SH_LDA, nullptr, 0);
        gbar(mygen);

        gemm_phase(sm, P.shh, P.shm, SH_LDA, 400,
                   P.fhh, P.fhm, FH_LDA,
                   P.W1h, P.W1m, 1120,
                   P.z, 4 * F_, psC, 1120, 4 * F_, 44, KS_CELL);
        gbar(mygen);
        pw_phase<KS_CELL>(sm, P.z, psC, P.b1, P.fh, P.fc, F_,
                          P.g1, P.bg1, P.gc1, P.bc1,
                          P.fhh, P.fhm, FH_LDA, P.hih, t);
        gbar(mygen);
    }

    // Recurrence done: help finish any remaining projection tiles.
    proj_loop(sm, P.hih, P.Woh, P.bout, P.out);
}

// ---------------------------------------------------------------------------
// Fused setup kernel
// ---------------------------------------------------------------------------
__global__ void setup_all(const float* __restrict__ W0, const float* __restrict__ WS,
                          const float* __restrict__ W1, const float* __restrict__ Wout,
                          const float* __restrict__ inputs)
{
    const long i0 = (long)blockIdx.x * blockDim.x + threadIdx.x;
    const long gsz = (long)gridDim.x * blockDim.x;
    const fp16 hz = __float2half(0.0f);

    for (long i = i0; i < 2800L * 832; i += gsz) {
        int n = (int)(i / 832), k = (int)(i % 832);
        float v = (k < 828) ? W0[(long)k * 2800 + n] : 0.0f;
        split2(v, g_W0h[i], g_W0m[i]);
    }
    for (long i = i0; i < 1600L * 1120; i += gsz) {
        int n = (int)(i / 1120), k = (int)(i % 1120);
        float v = 0.0f;
        if (k < 700)                   v = WS[(long)k * 1600 + n];
        else if (k >= 704 && k < 1104) v = WS[(long)(k - 4) * 1600 + n];
        split2(v, g_WSh[i], g_WSm[i]);
    }
    for (long i = i0; i < 2800L * 1120; i += gsz) {
        int n = (int)(i / 1120), k = (int)(i % 1120);
        float v = (k < 1100) ? W1[(long)k * 2800 + n] : 0.0f;
        split2(v, g_W1h[i], g_W1m[i]);
    }
    for (long i = i0; i < 10000L * 704; i += gsz) {
        int n = (int)(i / 704), k = (int)(i % 704);
        float v = (k < 700) ? Wout[(long)k * 10000 + n] : 0.0f;
        g_Woh[i] = __float2half_rn(v);
    }
    for (long i = i0; i < (long)B_ * T_ * E_; i += gsz) {
        fp16 h, m;
        split2(inputs[i], h, m);
        g_xh[i] = h; g_xm[i] = m;
    }
    if (i0 == 0) { g_bargen = 0u; g_ptk = 0u; }
    for (long j = i0; j < GRID_P * 8; j += gsz) g_flags[j] = 0u;
    for (long j = i0; j < B_ * F_; j += gsz) { g_fh[j] = 0.0f; g_fc[j] = 0.0f; }
    for (long j = i0; j < B_ * S_; j += gsz) { g_sh[j] = 0.0f; g_sc[j] = 0.0f; }
    for (long j = i0; j < B_ * FH_LDA; j += gsz) { g_fhh[j] = hz; g_fhm[j] = hz; }
    for (long j = i0; j < B_ * SH_LDA; j += gsz) { g_shh[j] = hz; g_shm[j] = hz; }
    for (long j = i0; j < B_ * T_ * 4; j += gsz) {
        size_t off = (size_t)(j >> 2) * HI_LDA + F_ + (j & 3);
        g_hih[off] = hz;
    }
}

__global__ void tail_copy(float* __restrict__ out, size_t out_total)
{
    int i = blockIdx.x * blockDim.x + threadIdx.x;
    const size_t base = (size_t)B_ * T_ * V_;
    const int nF = B_ * F_, nS = B_ * S_;
    const int total = 2 * nF + 2 * nS;
    if (i >= total) return;
    float v;
    size_t off = base + i;
    if (i < nF)               v = g_fh[i];
    else if (i < 2 * nF)      v = g_fc[i - nF];
    else if (i < 2 * nF + nS) v = g_sh[i - 2 * nF];
    else                      v = g_sc[i - 2 * nF - nS];
    if (off < out_total) out[off] = v;
}

// ---------------------------------------------------------------------------
// Launch
// ---------------------------------------------------------------------------
extern "C" void kernel_launch(void* const* d_in, const int* in_sizes, int n_in,
                              void* d_out, int out_size)
{
    const float* inputs = (const float*)d_in[0];
    const float* W0  = (const float*)d_in[1];
    const float* b0  = (const float*)d_in[2];
    const float* g0  = (const float*)d_in[3];
    const float* bg0 = (const float*)d_in[4];
    const float* gc0 = (const float*)d_in[5];
    const float* bc0 = (const float*)d_in[6];
    const float* W1  = (const float*)d_in[7];
    const float* b1  = (const float*)d_in[8];
    const float* g1  = (const float*)d_in[9];
    const float* bg1 = (const float*)d_in[10];
    const float* gc1 = (const float*)d_in[11];
    const float* bc1 = (const float*)d_in[12];
    const float* WS  = (const float*)d_in[13];
    const float* bS  = (const float*)d_in[14];
    const float* gS  = (const float*)d_in[15];
    const float* bgS = (const float*)d_in[16];
    const float* gcS = (const float*)d_in[17];
    const float* bcS = (const float*)d_in[18];
    const float* Wout = (const float*)d_in[19];
    const float* bout = (const float*)d_in[20];
    float* out = (float*)d_out;

    RecParams P;
    float *z, *zS;
    fp16 *Woh, *hih;
    cudaGetSymbolAddress((void**)&P.fh,  g_fh);  cudaGetSymbolAddress((void**)&P.fc,  g_fc);
    cudaGetSymbolAddress((void**)&P.sh,  g_sh);  cudaGetSymbolAddress((void**)&P.sc,  g_sc);
    cudaGetSymbolAddress((void**)&z,     g_z);   cudaGetSymbolAddress((void**)&zS,    g_zS);
    cudaGetSymbolAddress((void**)&P.xh,  g_xh);  cudaGetSymbolAddress((void**)&P.xm,  g_xm);
    cudaGetSymbolAddress((void**)&P.fhh, g_fhh); cudaGetSymbolAddress((void**)&P.fhm, g_fhm);
    cudaGetSymbolAddress((void**)&P.shh, g_shh); cudaGetSymbolAddress((void**)&P.shm, g_shm);
    cudaGetSymbolAddress((void**)&hih,   g_hih);
    cudaGetSymbolAddress((void**)&P.W0h, g_W0h); cudaGetSymbolAddress((void**)&P.W0m, g_W0m);
    cudaGetSymbolAddress((void**)&P.WSh, g_WSh); cudaGetSymbolAddress((void**)&P.WSm, g_WSm);
    cudaGetSymbolAddress((void**)&P.W1h, g_W1h); cudaGetSymbolAddress((void**)&P.W1m, g_W1m);
    cudaGetSymbolAddress((void**)&Woh,   g_Woh);
    P.z = z; P.zS = zS;
    P.hih = hih; P.Woh = Woh; P.bout = bout; P.out = out;
    P.b0 = b0; P.g0 = g0; P.bg0 = bg0; P.gc0 = gc0; P.bc0 = bc0;
    P.b1 = b1; P.g1 = g1; P.bg1 = bg1; P.gc1 = gc1; P.bc1 = bc1;
    P.bS = bS; P.gS = gS; P.bgS = bgS; P.gcS = gcS; P.bcS = bcS;

    cudaFuncSetAttribute(rec_persist, cudaFuncAttributeMaxDynamicSharedMemorySize, SMP);

    setup_all<<<1024, 256>>>(W0, WS, W1, Wout, inputs);

    // Recurrence + overlapped projection: ONE persistent kernel.
    rec_persist<<<GRID_ALL, 256, SMP>>>(P);

    {
        int total = 2 * B_ * F_ + 2 * B_ * S_;
        tail_copy<<<(total + 255) / 256, 256>>>(out, (size_t)out_size);
    }
}